// round 7
// baseline (speedup 1.0000x reference)
#include <cuda_runtime.h>
#include <cuda_bf16.h>
#include <mma.h>
#include <math.h>
#include <stdint.h>

using namespace nvcuda;

// ---------------------------------------------------------------------------
// QuanvolutionClassifier on GB300 (sm_103a, HMMA fallback path):
//   prep  : transpose-split W1 -> bf16 hi/lo [128, KP], theta trig
//   quanv : 4-qubit circuit per 2x2 patch -> feats bf16 hi/lo [B, KP]
//   gemm  : wmma bf16 split GEMM (AhBh+AhBl+AlBh, fp32 acc) + bias/relu
//           + 128->10 GEMM + log_softmax fused
// ---------------------------------------------------------------------------

#define MAX_B 4096
#define KP    832           // 784 padded to 13*64
#define NCH   13            // K chunks of 64

__device__ __align__(16) __nv_bfloat16 g_fh[MAX_B * KP];   // zero-init padding
__device__ __align__(16) __nv_bfloat16 g_fl[MAX_B * KP];
__device__ __align__(16) __nv_bfloat16 g_w1h[128 * KP];
__device__ __align__(16) __nv_bfloat16 g_w1l[128 * KP];
__device__ float2 g_ttrig[8];

// ============================== prep kernel ================================
// Tiled transpose W1[784,128] -> [128, KP] with bf16 hi/lo split.
__global__ void prep_kernel(const float* __restrict__ W1,
                            const float* __restrict__ theta)
{
    __shared__ float tile[32][33];
    int k0 = blockIdx.x * 32, n0 = blockIdx.y * 32;
    int tx = threadIdx.x, ty = threadIdx.y;   // 32 x 8
#pragma unroll
    for (int i = 0; i < 32; i += 8) {
        int k = k0 + ty + i, n = n0 + tx;
        tile[ty + i][tx] = (k < 784) ? W1[k * 128 + n] : 0.f;
    }
    __syncthreads();
#pragma unroll
    for (int i = 0; i < 32; i += 8) {
        int n = n0 + ty + i, k = k0 + tx;
        if (k < KP) {
            float v = tile[tx][ty + i];
            __nv_bfloat16 h = __float2bfloat16(v);
            __nv_bfloat16 l = __float2bfloat16(v - __bfloat162float(h));
            g_w1h[n * KP + k] = h;
            g_w1l[n * KP + k] = l;
        }
    }
    if (blockIdx.x == 0 && blockIdx.y == 0 && ty == 0 && tx < 8) {
        float c, s;
        sincosf(0.5f * theta[tx], &s, &c);
        g_ttrig[tx] = make_float2(c, s);
    }
}

// ============================== quanv kernel ===============================
__global__ __launch_bounds__(256) void quanv_kernel(
    const float* __restrict__ x, int B)
{
    int idx = blockIdx.x * blockDim.x + threadIdx.x;
    int total = B * 196;
    if (idx >= total) return;
    int b = idx / 196;
    int p = idx - b * 196;
    int r14 = p / 14;
    int c14 = p - r14 * 14;

    const float* xb = x + (size_t)b * 784 + (r14 * 2) * 28 + c14 * 2;
    float2 t0 = *reinterpret_cast<const float2*>(xb);
    float2 t1 = *reinterpret_cast<const float2*>(xb + 28);

    float c[4], s[4];
    __sincosf(0.5f * t0.x, &s[0], &c[0]);
    __sincosf(0.5f * t0.y, &s[1], &c[1]);
    __sincosf(0.5f * t1.x, &s[2], &c[2]);
    __sincosf(0.5f * t1.y, &s[3], &c[3]);

    float p01[4] = {c[0]*c[1], c[0]*s[1], s[0]*c[1], s[0]*s[1]};
    float p23[4] = {c[2]*c[3], c[2]*s[3], s[2]*c[3], s[2]*s[3]};
    float st[16];
#pragma unroll
    for (int i = 0; i < 16; i++) st[i] = p01[i >> 2] * p23[i & 3];

    float tc[8], ts[8];
#pragma unroll
    for (int t = 0; t < 8; t++) {
        float2 v = g_ttrig[t];
        tc[t] = v.x; ts[t] = v.y;
    }

#pragma unroll
    for (int l = 0; l < 2; l++) {
#pragma unroll
        for (int w = 0; w < 4; w++) {
            float cc = tc[l * 4 + w], ss = ts[l * 4 + w];
            int mask = 8 >> w;
#pragma unroll
            for (int i = 0; i < 16; i++) {
                if (i & mask) continue;
                int j = i | mask;
                float a0 = st[i], a1 = st[j];
                st[i] = cc * a0 - ss * a1;
                st[j] = ss * a0 + cc * a1;
            }
        }
#pragma unroll
        for (int w = 0; w < 4; w++) {
            int cm = 8 >> w;
            int tm = 8 >> ((w + 1) & 3);
#pragma unroll
            for (int i = 0; i < 16; i++) {
                if ((i & cm) && !(i & tm)) {
                    int j = i | tm;
                    float tt = st[i]; st[i] = st[j]; st[j] = tt;
                }
            }
        }
    }

    float q[16];
#pragma unroll
    for (int i = 0; i < 16; i++) q[i] = st[i] * st[i];
    float o[4];
#pragma unroll
    for (int w = 0; w < 4; w++) {
        int mask = 8 >> w;
        float z = 0.f;
#pragma unroll
        for (int i = 0; i < 16; i++) z += (i & mask) ? -q[i] : q[i];
        o[w] = z;
    }

    __nv_bfloat16 h[4], l[4];
#pragma unroll
    for (int w = 0; w < 4; w++) {
        h[w] = __float2bfloat16(o[w]);
        l[w] = __float2bfloat16(o[w] - __bfloat162float(h[w]));
    }
    size_t off = (size_t)b * KP + p * 4;
    *reinterpret_cast<__nv_bfloat162*>(&g_fh[off])     = __nv_bfloat162(h[0], h[1]);
    *reinterpret_cast<__nv_bfloat162*>(&g_fh[off + 2]) = __nv_bfloat162(h[2], h[3]);
    *reinterpret_cast<__nv_bfloat162*>(&g_fl[off])     = __nv_bfloat162(l[0], l[1]);
    *reinterpret_cast<__nv_bfloat162*>(&g_fl[off + 2]) = __nv_bfloat162(l[2], l[3]);
}

// =============================== gemm kernel ===============================
// Grid = B/32 CTAs x 256 thr. Per CTA: C[32x128] = feats_tile @ W1^T via wmma
// bf16 split. K chunks of 64, double-buffered smem, register prefetch.
#define ASTR 80                       // bf16 stride (160B, 16B-aligned granules)
#define A_PART (32 * ASTR * 2)        // 5120 B
#define B_PART (128 * ASTR * 2)       // 20480 B
#define BUF_B  (2 * A_PART + 2 * B_PART)   // 51200 B
#define DSMEM_B (2 * BUF_B)           // 102400 B
#define CSTR 136                      // fp32 C stride

__global__ __launch_bounds__(256, 1) void gemm_kernel(
    const __nv_bfloat16* __restrict__ fh, const __nv_bfloat16* __restrict__ fl,
    const __nv_bfloat16* __restrict__ wh, const __nv_bfloat16* __restrict__ wl,
    const float* __restrict__ b1, const float* __restrict__ W2,
    const float* __restrict__ b2, float* __restrict__ out, int B)
{
    extern __shared__ __align__(16) char db[];
    __shared__ float sW2t[1280];      // [q][128]
    __shared__ float sb1[128];

    int tid = threadIdx.x;
    int wid = tid >> 5;
    int row0 = blockIdx.x * 32;

    for (int i = tid; i < 1280; i += 256) {
        int qq = i >> 7, n = i & 127;
        sW2t[i] = W2[n * 10 + qq];
    }
    if (tid < 128) sb1[tid] = b1[tid];

    const uint4* fh4 = reinterpret_cast<const uint4*>(fh);
    const uint4* fl4 = reinterpret_cast<const uint4*>(fl);
    const uint4* wh4 = reinterpret_cast<const uint4*>(wh);
    const uint4* wl4 = reinterpret_cast<const uint4*>(wl);
    const int RSTR = KP / 8;          // 104 uint4 per source row

    int ar = tid >> 3, ac = tid & 7;  // A granule (256 granules per part)

    uint4 va_h, va_l, vb_h[4], vb_l[4];

    auto prefetch = [&](int kc) {
        size_t oa = (size_t)(row0 + ar) * RSTR + kc * 8 + ac;
        va_h = fh4[oa];
        va_l = fl4[oa];
#pragma unroll
        for (int i = 0; i < 4; i++) {
            int g = tid + i * 256;
            int r = g >> 3, cc = g & 7;
            size_t ob = (size_t)r * RSTR + kc * 8 + cc;
            vb_h[i] = wh4[ob];
            vb_l[i] = wl4[ob];
        }
    };
    auto store_buf = [&](int buf) {
        char* base = db + buf * BUF_B;
        *reinterpret_cast<uint4*>(base + ar * (ASTR * 2) + ac * 16) = va_h;
        *reinterpret_cast<uint4*>(base + A_PART + ar * (ASTR * 2) + ac * 16) = va_l;
#pragma unroll
        for (int i = 0; i < 4; i++) {
            int g = tid + i * 256;
            int r = g >> 3, cc = g & 7;
            *reinterpret_cast<uint4*>(base + 2 * A_PART + r * (ASTR * 2) + cc * 16) = vb_h[i];
            *reinterpret_cast<uint4*>(base + 2 * A_PART + B_PART + r * (ASTR * 2) + cc * 16) = vb_l[i];
        }
    };

    // warp tile assignment: m tile = wid&1, n tiles = (wid>>1)*2 .. +1
    int mt = wid & 1;
    int nt0 = (wid >> 1) * 2;

    wmma::fragment<wmma::accumulator, 16, 16, 16, float> acc[2];
    wmma::fill_fragment(acc[0], 0.f);
    wmma::fill_fragment(acc[1], 0.f);

    prefetch(0);
    store_buf(0);
    __syncthreads();

    for (int c = 0; c < NCH; c++) {
        if (c + 1 < NCH) prefetch(c + 1);

        const __nv_bfloat16* sAh = reinterpret_cast<const __nv_bfloat16*>(db + (c & 1) * BUF_B);
        const __nv_bfloat16* sAl = sAh + 32 * ASTR;
        const __nv_bfloat16* sBh = sAh + 64 * ASTR;
        const __nv_bfloat16* sBl = sAh + 64 * ASTR + 128 * ASTR;

#pragma unroll
        for (int ks = 0; ks < 4; ks++) {
            wmma::fragment<wmma::matrix_a, 16, 16, 16, __nv_bfloat16, wmma::row_major> ah, al;
            wmma::load_matrix_sync(ah, sAh + mt * 16 * ASTR + ks * 16, ASTR);
            wmma::load_matrix_sync(al, sAl + mt * 16 * ASTR + ks * 16, ASTR);
#pragma unroll
            for (int j = 0; j < 2; j++) {
                wmma::fragment<wmma::matrix_b, 16, 16, 16, __nv_bfloat16, wmma::col_major> bh, bl;
                wmma::load_matrix_sync(bh, sBh + (nt0 + j) * 16 * ASTR + ks * 16, ASTR);
                wmma::load_matrix_sync(bl, sBl + (nt0 + j) * 16 * ASTR + ks * 16, ASTR);
                wmma::mma_sync(acc[j], ah, bh, acc[j]);
                wmma::mma_sync(acc[j], ah, bl, acc[j]);
                wmma::mma_sync(acc[j], al, bh, acc[j]);
            }
        }
        __syncthreads();
        if (c + 1 < NCH) {
            store_buf((c + 1) & 1);
            __syncthreads();
        }
    }

    // ---- store C to smem (reuse buffer 0; all compute done, synced above)
    float* sC = reinterpret_cast<float*>(db);
    wmma::store_matrix_sync(sC + mt * 16 * CSTR + nt0 * 16, acc[0], CSTR, wmma::mem_row_major);
    wmma::store_matrix_sync(sC + mt * 16 * CSTR + (nt0 + 1) * 16, acc[1], CSTR, wmma::mem_row_major);
    __syncthreads();

    // ---- fused bias/relu + 128->10 GEMM + log_softmax (warp per 4 rows)
    int lane = tid & 31;
#pragma unroll
    for (int rr = 0; rr < 4; rr++) {
        int r = wid * 4 + rr;
        float hv[4];
#pragma unroll
        for (int j = 0; j < 4; j++) {
            int col = lane + 32 * j;
            float h = sC[r * CSTR + col] + sb1[col];
            hv[j] = h > 0.f ? h : 0.f;
        }
        float lg[10];
#pragma unroll
        for (int qq = 0; qq < 10; qq++) lg[qq] = 0.f;
#pragma unroll
        for (int j = 0; j < 4; j++)
#pragma unroll
            for (int qq = 0; qq < 10; qq++)
                lg[qq] = fmaf(hv[j], sW2t[qq * 128 + lane + 32 * j], lg[qq]);
#pragma unroll
        for (int off = 16; off; off >>= 1)
#pragma unroll
            for (int qq = 0; qq < 10; qq++)
                lg[qq] += __shfl_xor_sync(0xffffffffu, lg[qq], off);

        if (lane == 0) {
            int row = row0 + r;
            if (row < B) {
                float lv[10];
                float m = -1e30f;
#pragma unroll
                for (int qq = 0; qq < 10; qq++) {
                    lv[qq] = lg[qq] + __ldg(&b2[qq]);
                    m = fmaxf(m, lv[qq]);
                }
                float se = 0.f;
#pragma unroll
                for (int qq = 0; qq < 10; qq++) se += expf(lv[qq] - m);
                float lse = m + logf(se);
#pragma unroll
                for (int qq = 0; qq < 10; qq++)
                    out[(size_t)row * 10 + qq] = lv[qq] - lse;
            }
        }
    }
}

// ================================ launch ===================================
extern "C" void kernel_launch(void* const* d_in, const int* in_sizes, int n_in,
                              void* d_out, int out_size) {
    const float* x     = (const float*)d_in[0];   // [B, 784]
    const float* theta = (const float*)d_in[1];   // [2, 4]
    const float* W1    = (const float*)d_in[2];   // [784, 128]
    const float* b1    = (const float*)d_in[3];   // [128]
    const float* W2    = (const float*)d_in[4];   // [128, 10]
    const float* b2    = (const float*)d_in[5];   // [10]
    float* out = (float*)d_out;

    int B = in_sizes[0] / 784;
    if (B > MAX_B) B = MAX_B;

    __nv_bfloat16 *fh, *fl, *wh, *wl;
    cudaGetSymbolAddress((void**)&fh, g_fh);
    cudaGetSymbolAddress((void**)&fl, g_fl);
    cudaGetSymbolAddress((void**)&wh, g_w1h);
    cudaGetSymbolAddress((void**)&wl, g_w1l);

    cudaFuncSetAttribute(gemm_kernel,
                         cudaFuncAttributeMaxDynamicSharedMemorySize, DSMEM_B);

    prep_kernel<<<dim3(25, 4), dim3(32, 8)>>>(W1, theta);

    int total = B * 196;
    quanv_kernel<<<(total + 255) / 256, 256>>>(x, B);

    int mtiles = (B + 31) / 32;
    gemm_kernel<<<mtiles, 256, DSMEM_B>>>(fh, fl, wh, wl, b1, W2, b2, out, B);
}

// round 8
// speedup vs baseline: 1.4124x; 1.4124x over previous
#include <cuda_runtime.h>
#include <cuda_bf16.h>
#include <mma.h>
#include <math.h>
#include <stdint.h>

using namespace nvcuda;

// ---------------------------------------------------------------------------
// QuanvolutionClassifier (sm_103a, HMMA path):
//   quanv+prep : circuit per patch -> feats bf16 hi/lo; extra blocks split W1
//   gemm       : wmma bf16 split GEMM (AhBh+AhBl+AlBh, fp32 acc), cp.async
//                double-buffered, conflict-free ldmatrix (176B stride),
//                fused bias/relu + 128->10 GEMM + log_softmax
// ---------------------------------------------------------------------------

#define MAX_B 4096
#define KP    832           // 784 padded to 13*64
#define NCH   13            // K chunks of 64

__device__ __align__(16) __nv_bfloat16 g_fh[MAX_B * KP];   // zero-init padding
__device__ __align__(16) __nv_bfloat16 g_fl[MAX_B * KP];
__device__ __align__(16) __nv_bfloat16 g_w1h[128 * KP];
__device__ __align__(16) __nv_bfloat16 g_w1l[128 * KP];

// ========================= helpers =========================================
__device__ __forceinline__ uint32_t smem_u32(const void* p) {
    uint32_t a;
    asm("{ .reg .u64 t; cvta.to.shared.u64 t, %1; cvt.u32.u64 %0, t; }"
        : "=r"(a) : "l"(p));
    return a;
}
__device__ __forceinline__ void cp16(uint32_t dst, const void* src) {
    asm volatile("cp.async.cg.shared.global [%0], [%1], 16;"
                 :: "r"(dst), "l"(src) : "memory");
}
#define CP_COMMIT() asm volatile("cp.async.commit_group;" ::: "memory")
template <int N> __device__ __forceinline__ void cp_wait() {
    asm volatile("cp.async.wait_group %0;" :: "n"(N) : "memory");
}

// ===================== quanv + W1-split kernel =============================
// Blocks [0, qblocks): quanv.  Blocks [qblocks, qblocks+100): W1 transpose-split.
__global__ __launch_bounds__(256) void quanv_kernel(
    const float* __restrict__ x, const float* __restrict__ theta,
    const float* __restrict__ W1, int B, int qblocks)
{
    if ((int)blockIdx.x >= qblocks) {
        // ---- W1 split: tile t covers k0..k0+31 x n0..n0+31
        __shared__ float tile[32][33];
        int t = blockIdx.x - qblocks;          // 0..99  (25 x 4)
        int k0 = (t % 25) * 32, n0 = (t / 25) * 32;
        int tx = threadIdx.x & 31, ty = threadIdx.x >> 5;   // 32 x 8
#pragma unroll
        for (int i = 0; i < 32; i += 8) {
            int k = k0 + ty + i;
            tile[ty + i][tx] = (k < 784) ? W1[k * 128 + n0 + tx] : 0.f;
        }
        __syncthreads();
#pragma unroll
        for (int i = 0; i < 32; i += 8) {
            int n = n0 + ty + i, k = k0 + tx;
            float v = tile[tx][ty + i];
            __nv_bfloat16 h = __float2bfloat16(v);
            __nv_bfloat16 l = __float2bfloat16(v - __bfloat162float(h));
            g_w1h[n * KP + k] = h;
            g_w1l[n * KP + k] = l;
        }
        return;
    }

    int idx = blockIdx.x * blockDim.x + threadIdx.x;
    int total = B * 196;
    if (idx >= total) return;
    int b = idx / 196;
    int p = idx - b * 196;
    int r14 = p / 14;
    int c14 = p - r14 * 14;

    const float* xb = x + (size_t)b * 784 + (r14 * 2) * 28 + c14 * 2;
    float2 t0 = *reinterpret_cast<const float2*>(xb);
    float2 t1 = *reinterpret_cast<const float2*>(xb + 28);

    float c[4], s[4];
    __sincosf(0.5f * t0.x, &s[0], &c[0]);
    __sincosf(0.5f * t0.y, &s[1], &c[1]);
    __sincosf(0.5f * t1.x, &s[2], &c[2]);
    __sincosf(0.5f * t1.y, &s[3], &c[3]);

    float p01[4] = {c[0]*c[1], c[0]*s[1], s[0]*c[1], s[0]*s[1]};
    float p23[4] = {c[2]*c[3], c[2]*s[3], s[2]*c[3], s[2]*s[3]};
    float st[16];
#pragma unroll
    for (int i = 0; i < 16; i++) st[i] = p01[i >> 2] * p23[i & 3];

    float tc[8], ts[8];
#pragma unroll
    for (int t = 0; t < 8; t++)
        __sincosf(0.5f * __ldg(&theta[t]), &ts[t], &tc[t]);

#pragma unroll
    for (int l = 0; l < 2; l++) {
#pragma unroll
        for (int w = 0; w < 4; w++) {
            float cc = tc[l * 4 + w], ss = ts[l * 4 + w];
            int mask = 8 >> w;
#pragma unroll
            for (int i = 0; i < 16; i++) {
                if (i & mask) continue;
                int j = i | mask;
                float a0 = st[i], a1 = st[j];
                st[i] = cc * a0 - ss * a1;
                st[j] = ss * a0 + cc * a1;
            }
        }
#pragma unroll
        for (int w = 0; w < 4; w++) {
            int cm = 8 >> w;
            int tm = 8 >> ((w + 1) & 3);
#pragma unroll
            for (int i = 0; i < 16; i++) {
                if ((i & cm) && !(i & tm)) {
                    int j = i | tm;
                    float tt = st[i]; st[i] = st[j]; st[j] = tt;
                }
            }
        }
    }

    float q[16];
#pragma unroll
    for (int i = 0; i < 16; i++) q[i] = st[i] * st[i];
    float o[4];
#pragma unroll
    for (int w = 0; w < 4; w++) {
        int mask = 8 >> w;
        float z = 0.f;
#pragma unroll
        for (int i = 0; i < 16; i++) z += (i & mask) ? -q[i] : q[i];
        o[w] = z;
    }

    __nv_bfloat16 h[4], l[4];
#pragma unroll
    for (int w = 0; w < 4; w++) {
        h[w] = __float2bfloat16(o[w]);
        l[w] = __float2bfloat16(o[w] - __bfloat162float(h[w]));
    }
    size_t off = (size_t)b * KP + p * 4;
    *reinterpret_cast<__nv_bfloat162*>(&g_fh[off])     = __nv_bfloat162(h[0], h[1]);
    *reinterpret_cast<__nv_bfloat162*>(&g_fh[off + 2]) = __nv_bfloat162(h[2], h[3]);
    *reinterpret_cast<__nv_bfloat162*>(&g_fl[off])     = __nv_bfloat162(l[0], l[1]);
    *reinterpret_cast<__nv_bfloat162*>(&g_fl[off + 2]) = __nv_bfloat162(l[2], l[3]);
}

// =============================== gemm kernel ===============================
// Grid = B/32 CTAs x 256 thr. C[32x128] = feats @ W1^T, wmma bf16 split.
// ASTR=88 bf16 (176B) -> ldmatrix rows hit banks 12r mod 32 : conflict-free.
#define ASTR   88
#define A_BYTES (32 * ASTR * 2)                  // 5632
#define B_BYTES (128 * ASTR * 2)                 // 22528
#define BUF_B   (2 * A_BYTES + 2 * B_BYTES)      // 56320
#define DSMEM_B (2 * BUF_B)                      // 112640
#define CSTR 136

__global__ __launch_bounds__(256, 1) void gemm_kernel(
    const __nv_bfloat16* __restrict__ fh, const __nv_bfloat16* __restrict__ fl,
    const __nv_bfloat16* __restrict__ wh, const __nv_bfloat16* __restrict__ wl,
    const float* __restrict__ b1, const float* __restrict__ W2,
    const float* __restrict__ b2, float* __restrict__ out, int B)
{
    extern __shared__ __align__(16) char db[];
    __shared__ float sW2t[1280];      // [q][128]
    __shared__ float sb1[128];

    int tid = threadIdx.x;
    int wid = tid >> 5;
    int row0 = blockIdx.x * 32;

    for (int i = tid; i < 1280; i += 256) {
        int qq = i >> 7, n = i & 127;
        sW2t[i] = W2[n * 10 + qq];
    }
    if (tid < 128) sb1[tid] = b1[tid];

    const uint4* fh4 = reinterpret_cast<const uint4*>(fh);
    const uint4* fl4 = reinterpret_cast<const uint4*>(fl);
    const uint4* wh4 = reinterpret_cast<const uint4*>(wh);
    const uint4* wl4 = reinterpret_cast<const uint4*>(wl);
    const int RSTR = KP / 8;          // 104 uint4 per source row

    uint32_t sbase = smem_u32(db);
    int ar = tid >> 3, ac = tid & 7;

    auto issue = [&](int kc, int buf) {
        uint32_t base = sbase + buf * BUF_B;
        size_t oa = (size_t)(row0 + ar) * RSTR + kc * 8 + ac;
        uint32_t da = base + ar * 176 + ac * 16;
        cp16(da, fh4 + oa);
        cp16(da + A_BYTES, fl4 + oa);
#pragma unroll
        for (int i = 0; i < 4; i++) {
            int g = tid + i * 256;
            int r = g >> 3, cc = g & 7;
            size_t ob = (size_t)r * RSTR + kc * 8 + cc;
            uint32_t dbb = base + 2 * A_BYTES + r * 176 + cc * 16;
            cp16(dbb, wh4 + ob);
            cp16(dbb + B_BYTES, wl4 + ob);
        }
    };

    int mt = wid & 1;
    int nt0 = (wid >> 1) * 2;

    wmma::fragment<wmma::accumulator, 16, 16, 16, float> acc[2];
    wmma::fill_fragment(acc[0], 0.f);
    wmma::fill_fragment(acc[1], 0.f);

    issue(0, 0); CP_COMMIT();
    issue(1, 1); CP_COMMIT();

    for (int c = 0; c < NCH; c++) {
        if (c == NCH - 1) cp_wait<0>(); else cp_wait<1>();
        __syncthreads();

        const __nv_bfloat16* sAh =
            reinterpret_cast<const __nv_bfloat16*>(db + (c & 1) * BUF_B);
        const __nv_bfloat16* sAl = sAh + 32 * ASTR;
        const __nv_bfloat16* sBh = sAh + 64 * ASTR;
        const __nv_bfloat16* sBl = sBh + 128 * ASTR;

#pragma unroll
        for (int ks = 0; ks < 4; ks++) {
            wmma::fragment<wmma::matrix_a, 16, 16, 16, __nv_bfloat16, wmma::row_major> ah, al;
            wmma::load_matrix_sync(ah, sAh + mt * 16 * ASTR + ks * 16, ASTR);
            wmma::load_matrix_sync(al, sAl + mt * 16 * ASTR + ks * 16, ASTR);
#pragma unroll
            for (int j = 0; j < 2; j++) {
                wmma::fragment<wmma::matrix_b, 16, 16, 16, __nv_bfloat16, wmma::col_major> bh, bl;
                wmma::load_matrix_sync(bh, sBh + (nt0 + j) * 16 * ASTR + ks * 16, ASTR);
                wmma::load_matrix_sync(bl, sBl + (nt0 + j) * 16 * ASTR + ks * 16, ASTR);
                wmma::mma_sync(acc[j], ah, bh, acc[j]);
                wmma::mma_sync(acc[j], ah, bl, acc[j]);
                wmma::mma_sync(acc[j], al, bh, acc[j]);
            }
        }
        __syncthreads();
        if (c + 2 < NCH) { issue(c + 2, c & 1); CP_COMMIT(); }
    }

    // ---- store C (reuse buffer 0)
    float* sC = reinterpret_cast<float*>(db);
    wmma::store_matrix_sync(sC + mt * 16 * CSTR + nt0 * 16, acc[0], CSTR, wmma::mem_row_major);
    wmma::store_matrix_sync(sC + mt * 16 * CSTR + (nt0 + 1) * 16, acc[1], CSTR, wmma::mem_row_major);
    __syncthreads();

    // ---- fused bias/relu + 128->10 GEMM + log_softmax (warp per 4 rows)
    int lane = tid & 31;
#pragma unroll
    for (int rr = 0; rr < 4; rr++) {
        int r = wid * 4 + rr;
        float hv[4];
#pragma unroll
        for (int j = 0; j < 4; j++) {
            int col = lane + 32 * j;
            float h = sC[r * CSTR + col] + sb1[col];
            hv[j] = h > 0.f ? h : 0.f;
        }
        float lg[10];
#pragma unroll
        for (int qq = 0; qq < 10; qq++) lg[qq] = 0.f;
#pragma unroll
        for (int j = 0; j < 4; j++)
#pragma unroll
            for (int qq = 0; qq < 10; qq++)
                lg[qq] = fmaf(hv[j], sW2t[qq * 128 + lane + 32 * j], lg[qq]);
#pragma unroll
        for (int off = 16; off; off >>= 1)
#pragma unroll
            for (int qq = 0; qq < 10; qq++)
                lg[qq] += __shfl_xor_sync(0xffffffffu, lg[qq], off);

        if (lane == 0) {
            int row = row0 + r;
            if (row < B) {
                float lv[10];
                float m = -1e30f;
#pragma unroll
                for (int qq = 0; qq < 10; qq++) {
                    lv[qq] = lg[qq] + __ldg(&b2[qq]);
                    m = fmaxf(m, lv[qq]);
                }
                float se = 0.f;
#pragma unroll
                for (int qq = 0; qq < 10; qq++) se += expf(lv[qq] - m);
                float lse = m + logf(se);
#pragma unroll
                for (int qq = 0; qq < 10; qq++)
                    out[(size_t)row * 10 + qq] = lv[qq] - lse;
            }
        }
    }
}

// ================================ launch ===================================
extern "C" void kernel_launch(void* const* d_in, const int* in_sizes, int n_in,
                              void* d_out, int out_size) {
    const float* x     = (const float*)d_in[0];   // [B, 784]
    const float* theta = (const float*)d_in[1];   // [2, 4]
    const float* W1    = (const float*)d_in[2];   // [784, 128]
    const float* b1    = (const float*)d_in[3];   // [128]
    const float* W2    = (const float*)d_in[4];   // [128, 10]
    const float* b2    = (const float*)d_in[5];   // [10]
    float* out = (float*)d_out;

    int B = in_sizes[0] / 784;
    if (B > MAX_B) B = MAX_B;

    __nv_bfloat16 *fh, *fl, *wh, *wl;
    cudaGetSymbolAddress((void**)&fh, g_fh);
    cudaGetSymbolAddress((void**)&fl, g_fl);
    cudaGetSymbolAddress((void**)&wh, g_w1h);
    cudaGetSymbolAddress((void**)&wl, g_w1l);

    cudaFuncSetAttribute(gemm_kernel,
                         cudaFuncAttributeMaxDynamicSharedMemorySize, DSMEM_B);

    int qblocks = (B * 196 + 255) / 256;
    quanv_kernel<<<qblocks + 100, 256>>>(x, theta, W1, B, qblocks);

    int mtiles = (B + 31) / 32;
    gemm_kernel<<<mtiles, 256, DSMEM_B>>>(fh, fl, wh, wl, b1, W2, b2, out, B);
}

// round 10
// speedup vs baseline: 1.4608x; 1.0342x over previous
#include <cuda_runtime.h>
#include <cuda_bf16.h>
#include <mma.h>
#include <math.h>
#include <stdint.h>

using namespace nvcuda;

// ---------------------------------------------------------------------------
// QuanvolutionClassifier (sm_103a, HMMA path):
//   quanv+prep : circuit per patch -> feats bf16 hi/lo; extra blocks split W1
//   gemm       : 512-thread CTA, intra-CTA split-K (2 groups, named barriers),
//                wmma bf16 split GEMM (AhBh+AhBl+AlBh, fp32 acc), cp.async
//                double-buffered per group, fused epilogue.
//   FIX vs R8 : full-CTA __syncthreads() BEFORE C stores (C staging region
//               overlaps the other group's live double-buffers).
// ---------------------------------------------------------------------------

#define MAX_B 4096
#define KP    832           // 784 padded (13*64 = 26*32)
#define NCHK  26            // K chunks of 32
#define HCHK  13            // chunks per group

__device__ __align__(16) __nv_bfloat16 g_fh[MAX_B * KP];   // zero-init padding
__device__ __align__(16) __nv_bfloat16 g_fl[MAX_B * KP];
__device__ __align__(16) __nv_bfloat16 g_w1h[128 * KP];
__device__ __align__(16) __nv_bfloat16 g_w1l[128 * KP];

// ========================= helpers =========================================
__device__ __forceinline__ uint32_t smem_u32(const void* p) {
    uint32_t a;
    asm("{ .reg .u64 t; cvta.to.shared.u64 t, %1; cvt.u32.u64 %0, t; }"
        : "=r"(a) : "l"(p));
    return a;
}
__device__ __forceinline__ void cp16(uint32_t dst, const void* src) {
    asm volatile("cp.async.cg.shared.global [%0], [%1], 16;"
                 :: "r"(dst), "l"(src) : "memory");
}
#define CP_COMMIT() asm volatile("cp.async.commit_group;" ::: "memory")
template <int N> __device__ __forceinline__ void cp_wait() {
    asm volatile("cp.async.wait_group %0;" :: "n"(N) : "memory");
}
__device__ __forceinline__ void gbar(int id) {
    asm volatile("bar.sync %0, 256;" :: "r"(id) : "memory");
}

// ===================== quanv + W1-split kernel =============================
__global__ __launch_bounds__(256) void quanv_kernel(
    const float* __restrict__ x, const float* __restrict__ theta,
    const float* __restrict__ W1, int B, int qblocks)
{
    if ((int)blockIdx.x >= qblocks) {
        // ---- W1 split: transpose tile 32x32
        __shared__ float tile[32][33];
        int t = blockIdx.x - qblocks;          // 0..99 (25 x 4)
        int k0 = (t % 25) * 32, n0 = (t / 25) * 32;
        int tx = threadIdx.x & 31, ty = threadIdx.x >> 5;
#pragma unroll
        for (int i = 0; i < 32; i += 8) {
            int k = k0 + ty + i;
            tile[ty + i][tx] = (k < 784) ? W1[k * 128 + n0 + tx] : 0.f;
        }
        __syncthreads();
#pragma unroll
        for (int i = 0; i < 32; i += 8) {
            int n = n0 + ty + i, k = k0 + tx;
            float v = tile[tx][ty + i];
            __nv_bfloat16 h = __float2bfloat16(v);
            __nv_bfloat16 l = __float2bfloat16(v - __bfloat162float(h));
            g_w1h[n * KP + k] = h;
            g_w1l[n * KP + k] = l;
        }
        return;
    }

    // theta trig once per block (8 sincos instead of per-thread)
    __shared__ float2 sTrig[8];
    if (threadIdx.x < 8) {
        float c, s;
        __sincosf(0.5f * __ldg(&theta[threadIdx.x]), &s, &c);
        sTrig[threadIdx.x] = make_float2(c, s);
    }
    __syncthreads();

    int idx = blockIdx.x * blockDim.x + threadIdx.x;
    int total = B * 196;
    if (idx >= total) return;
    int b = idx / 196;
    int p = idx - b * 196;
    int r14 = p / 14;
    int c14 = p - r14 * 14;

    const float* xb = x + (size_t)b * 784 + (r14 * 2) * 28 + c14 * 2;
    float2 t0 = *reinterpret_cast<const float2*>(xb);
    float2 t1 = *reinterpret_cast<const float2*>(xb + 28);

    float c[4], s[4];
    __sincosf(0.5f * t0.x, &s[0], &c[0]);
    __sincosf(0.5f * t0.y, &s[1], &c[1]);
    __sincosf(0.5f * t1.x, &s[2], &c[2]);
    __sincosf(0.5f * t1.y, &s[3], &c[3]);

    float p01[4] = {c[0]*c[1], c[0]*s[1], s[0]*c[1], s[0]*s[1]};
    float p23[4] = {c[2]*c[3], c[2]*s[3], s[2]*c[3], s[2]*s[3]};
    float st[16];
#pragma unroll
    for (int i = 0; i < 16; i++) st[i] = p01[i >> 2] * p23[i & 3];

#pragma unroll
    for (int l = 0; l < 2; l++) {
#pragma unroll
        for (int w = 0; w < 4; w++) {
            float2 v = sTrig[l * 4 + w];
            float cc = v.x, ss = v.y;
            int mask = 8 >> w;
#pragma unroll
            for (int i = 0; i < 16; i++) {
                if (i & mask) continue;
                int j = i | mask;
                float a0 = st[i], a1 = st[j];
                st[i] = cc * a0 - ss * a1;
                st[j] = ss * a0 + cc * a1;
            }
        }
#pragma unroll
        for (int w = 0; w < 4; w++) {
            int cm = 8 >> w;
            int tm = 8 >> ((w + 1) & 3);
#pragma unroll
            for (int i = 0; i < 16; i++) {
                if ((i & cm) && !(i & tm)) {
                    int j = i | tm;
                    float tt = st[i]; st[i] = st[j]; st[j] = tt;
                }
            }
        }
    }

    float q[16];
#pragma unroll
    for (int i = 0; i < 16; i++) q[i] = st[i] * st[i];
    float o[4];
#pragma unroll
    for (int w = 0; w < 4; w++) {
        int mask = 8 >> w;
        float z = 0.f;
#pragma unroll
        for (int i = 0; i < 16; i++) z += (i & mask) ? -q[i] : q[i];
        o[w] = z;
    }

    __nv_bfloat16 h[4], l[4];
#pragma unroll
    for (int w = 0; w < 4; w++) {
        h[w] = __float2bfloat16(o[w]);
        l[w] = __float2bfloat16(o[w] - __bfloat162float(h[w]));
    }
    size_t off = (size_t)b * KP + p * 4;
    *reinterpret_cast<__nv_bfloat162*>(&g_fh[off])     = __nv_bfloat162(h[0], h[1]);
    *reinterpret_cast<__nv_bfloat162*>(&g_fh[off + 2]) = __nv_bfloat162(h[2], h[3]);
    *reinterpret_cast<__nv_bfloat162*>(&g_fl[off])     = __nv_bfloat162(l[0], l[1]);
    *reinterpret_cast<__nv_bfloat162*>(&g_fl[off + 2]) = __nv_bfloat162(l[2], l[3]);
}

// =============================== gemm kernel ===============================
// Grid = B/32 CTAs x 512 thr (2 K-groups of 8 warps). C[32x128].
// K-chunk 32: ASTR=40 bf16 (80B) -> LDSM banks 20r mod 32, conflict-free.
#define ASTR   40
#define AH_OFF 0
#define AL_OFF 2560
#define BH_OFF 5120
#define BL_OFF 15360
#define BUF_B  25600
#define GRP_B  (2 * BUF_B)            // 51200 per group (2 stages)
#define DSMEM_B (2 * GRP_B)           // 102400
#define CSTR 132

__global__ __launch_bounds__(512, 1) void gemm_kernel(
    const __nv_bfloat16* __restrict__ fh, const __nv_bfloat16* __restrict__ fl,
    const __nv_bfloat16* __restrict__ wh, const __nv_bfloat16* __restrict__ wl,
    const float* __restrict__ b1, const float* __restrict__ W2,
    const float* __restrict__ b2, float* __restrict__ out, int B)
{
    extern __shared__ __align__(16) char db[];
    __shared__ float sW2t[1280];      // [q][128]
    __shared__ float sb1[128];

    int tid = threadIdx.x;
    int wid = tid >> 5;
    int lane = tid & 31;
    int g = wid >> 3;                 // K group 0/1
    int gw = wid & 7;                 // warp in group
    int gtid = tid & 255;
    int row0 = blockIdx.x * 32;

    for (int i = tid; i < 1280; i += 512) {
        int qq = i >> 7, n = i & 127;
        sW2t[i] = W2[n * 10 + qq];
    }
    if (tid < 128) sb1[tid] = b1[tid];

    const uint4* fh4 = reinterpret_cast<const uint4*>(fh);
    const uint4* fl4 = reinterpret_cast<const uint4*>(fl);
    const uint4* wh4 = reinterpret_cast<const uint4*>(wh);
    const uint4* wl4 = reinterpret_cast<const uint4*>(wl);
    const int RSTR = KP / 8;          // 104 uint4 per source row

    uint32_t gbase = smem_u32(db) + g * GRP_B;

    // per-thread staging (per group-chunk, 256 threads):
    //   A: gtid<128 -> Ah granule ; else Al granule (r=ag>>2, c=ag&3)
    //   B: Bh granules 2*gtid, 2*gtid+1 ; Bl same
    int ag = gtid & 127;
    int a_r = ag >> 2, a_c = ag & 3;
    bool a_hi = gtid < 128;

    auto issue = [&](int kc, int buf) {
        uint32_t base = gbase + buf * BUF_B;
        size_t oa = (size_t)(row0 + a_r) * RSTR + kc * 4 + a_c;
        uint32_t da = base + (a_hi ? AH_OFF : AL_OFF) + a_r * 80 + a_c * 16;
        cp16(da, (a_hi ? fh4 : fl4) + oa);
#pragma unroll
        for (int i = 0; i < 2; i++) {
            int bg = gtid * 2 + i;
            int r = bg >> 2, cc = bg & 3;
            size_t ob = (size_t)r * RSTR + kc * 4 + cc;
            uint32_t dbb = base + r * 80 + cc * 16;
            cp16(dbb + BH_OFF, wh4 + ob);
            cp16(dbb + BL_OFF, wl4 + ob);
        }
    };

    int mt = gw & 1;
    int nt0 = (gw >> 1) * 2;

    wmma::fragment<wmma::accumulator, 16, 16, 16, float> acc[2];
    wmma::fill_fragment(acc[0], 0.f);
    wmma::fill_fragment(acc[1], 0.f);

    int kc0 = g * HCHK;
    issue(kc0 + 0, 0); CP_COMMIT();
    issue(kc0 + 1, 1); CP_COMMIT();

    for (int i = 0; i < HCHK; i++) {
        if (i == HCHK - 1) cp_wait<0>(); else cp_wait<1>();
        gbar(1 + g);

        const __nv_bfloat16* sAh =
            reinterpret_cast<const __nv_bfloat16*>(db + g * GRP_B + (i & 1) * BUF_B);
        const __nv_bfloat16* sAl = sAh + 32 * ASTR;
        const __nv_bfloat16* sBh = sAh + 64 * ASTR;
        const __nv_bfloat16* sBl = sBh + 128 * ASTR;

#pragma unroll
        for (int ks = 0; ks < 2; ks++) {
            wmma::fragment<wmma::matrix_a, 16, 16, 16, __nv_bfloat16, wmma::row_major> ah, al;
            wmma::load_matrix_sync(ah, sAh + mt * 16 * ASTR + ks * 16, ASTR);
            wmma::load_matrix_sync(al, sAl + mt * 16 * ASTR + ks * 16, ASTR);
#pragma unroll
            for (int j = 0; j < 2; j++) {
                wmma::fragment<wmma::matrix_b, 16, 16, 16, __nv_bfloat16, wmma::col_major> bh, bl;
                wmma::load_matrix_sync(bh, sBh + (nt0 + j) * 16 * ASTR + ks * 16, ASTR);
                wmma::load_matrix_sync(bl, sBl + (nt0 + j) * 16 * ASTR + ks * 16, ASTR);
                wmma::mma_sync(acc[j], ah, bh, acc[j]);
                wmma::mma_sync(acc[j], ah, bl, acc[j]);
                wmma::mma_sync(acc[j], al, bh, acc[j]);
            }
        }
        gbar(1 + g);
        if (i + 2 < HCHK) { issue(kc0 + i + 2, i & 1); CP_COMMIT(); }
    }

    // ---- FIX: both groups must finish reading their buffers before C staging
    // overwrites smem (group 1's C region overlaps group 0's buffers).
    __syncthreads();

    float* sC = reinterpret_cast<float*>(db);            // 2 x [32][CSTR]
    float* sCg = sC + g * 32 * CSTR;
    wmma::store_matrix_sync(sCg + mt * 16 * CSTR + nt0 * 16, acc[0], CSTR, wmma::mem_row_major);
    wmma::store_matrix_sync(sCg + mt * 16 * CSTR + (nt0 + 1) * 16, acc[1], CSTR, wmma::mem_row_major);
    __syncthreads();

    // warp per 2 rows (16 warps x 2 = 32 rows); reduce the two K-halves
    const float* sC0 = sC;
    const float* sC1 = sC + 32 * CSTR;
#pragma unroll
    for (int rr = 0; rr < 2; rr++) {
        int r = wid * 2 + rr;
        float hv[4];
#pragma unroll
        for (int j = 0; j < 4; j++) {
            int col = lane + 32 * j;
            float h = sC0[r * CSTR + col] + sC1[r * CSTR + col] + sb1[col];
            hv[j] = h > 0.f ? h : 0.f;
        }
        float lg[10];
#pragma unroll
        for (int qq = 0; qq < 10; qq++) lg[qq] = 0.f;
#pragma unroll
        for (int j = 0; j < 4; j++)
#pragma unroll
            for (int qq = 0; qq < 10; qq++)
                lg[qq] = fmaf(hv[j], sW2t[qq * 128 + lane + 32 * j], lg[qq]);
#pragma unroll
        for (int off = 16; off; off >>= 1)
#pragma unroll
            for (int qq = 0; qq < 10; qq++)
                lg[qq] += __shfl_xor_sync(0xffffffffu, lg[qq], off);

        if (lane == 0) {
            int row = row0 + r;
            if (row < B) {
                float lv[10];
                float m = -1e30f;
#pragma unroll
                for (int qq = 0; qq < 10; qq++) {
                    lv[qq] = lg[qq] + __ldg(&b2[qq]);
                    m = fmaxf(m, lv[qq]);
                }
                float se = 0.f;
#pragma unroll
                for (int qq = 0; qq < 10; qq++) se += expf(lv[qq] - m);
                float lse = m + logf(se);
#pragma unroll
                for (int qq = 0; qq < 10; qq++)
                    out[(size_t)row * 10 + qq] = lv[qq] - lse;
            }
        }
    }
}

// ================================ launch ===================================
extern "C" void kernel_launch(void* const* d_in, const int* in_sizes, int n_in,
                              void* d_out, int out_size) {
    const float* x     = (const float*)d_in[0];   // [B, 784]
    const float* theta = (const float*)d_in[1];   // [2, 4]
    const float* W1    = (const float*)d_in[2];   // [784, 128]
    const float* b1    = (const float*)d_in[3];   // [128]
    const float* W2    = (const float*)d_in[4];   // [128, 10]
    const float* b2    = (const float*)d_in[5];   // [10]
    float* out = (float*)d_out;

    int B = in_sizes[0] / 784;
    if (B > MAX_B) B = MAX_B;

    __nv_bfloat16 *fh, *fl, *wh, *wl;
    cudaGetSymbolAddress((void**)&fh, g_fh);
    cudaGetSymbolAddress((void**)&fl, g_fl);
    cudaGetSymbolAddress((void**)&wh, g_w1h);
    cudaGetSymbolAddress((void**)&wl, g_w1l);

    cudaFuncSetAttribute(gemm_kernel,
                         cudaFuncAttributeMaxDynamicSharedMemorySize, DSMEM_B);

    int qblocks = (B * 196 + 255) / 256;
    quanv_kernel<<<qblocks + 100, 256>>>(x, theta, W1, B, qblocks);

    int mtiles = (B + 31) / 32;
    gemm_kernel<<<mtiles, 512, DSMEM_B>>>(fh, fl, wh, wl, b1, W2, b2, out, B);
}